// round 6
// baseline (speedup 1.0000x reference)
#include <cuda_runtime.h>
#include <math.h>

// Problem caps (N=100000, E=800000 per setup_inputs; small safety margin)
#define NCAP 100352
#define ECAP 802816
#define ETCAP (ECAP + NCAP)

// ---------------- device scratch (static, no allocation) ----------------
__device__ float g_h  [(size_t)NCAP * 128];   // per-layer transformed features
__device__ float g_x1 [(size_t)NCAP * 128];   // layer-1 output
__device__ float g_x2 [(size_t)NCAP * 128];   // layer-2 output
__device__ float g_agg[(size_t)NCAP * 512];   // layer-3 weighted x2 aggregate
__device__ float g_ss [NCAP * 4];             // s_src per node/head
__device__ float g_sd [NCAP * 4];             // s_dst per node/head
__device__ int   g_cnt [NCAP];
__device__ int   g_scan[NCAP];
__device__ int   g_bsum[1024];
__device__ int   g_off [NCAP + 1];
__device__ int   g_cur [NCAP];
__device__ int   g_csrc[ETCAP];
__device__ float g_ws[128 * 4];               // W3_h @ a_src3_h
__device__ float g_wd[128 * 4];               // W3_h @ a_dst3_h
__device__ int   g_i64;                       // 1 if edge_index is int64, 0 if int32

__device__ __forceinline__ float lrelu(float e) { return e > 0.f ? e : 0.2f * e; }

__device__ __forceinline__ int edge_at(const void* ei, int idx) {
    if (g_i64) return (int)((const long long*)ei)[idx];
    return ((const int*)ei)[idx];
}

// ---------------- edge dtype detection ----------------
__global__ void k_detect(const int* __restrict__ ei32, int nsamp) {
    __shared__ int any;
    if (threadIdx.x == 0) any = 0;
    __syncthreads();
    for (int i = threadIdx.x * 2 + 1; i < nsamp; i += 512)
        if (ei32[i] != 0) { any = 1; break; }
    __syncthreads();
    if (threadIdx.x == 0) g_i64 = any ? 0 : 1;
}

// ---------------- CSR build ----------------
__global__ void k_init_cnt(int N) {
    int i = blockIdx.x * blockDim.x + threadIdx.x;
    if (i < N) g_cnt[i] = 1;   // self loop
}

__global__ void k_hist(const void* __restrict__ ei, int E, int N) {
    int e = blockIdx.x * blockDim.x + threadIdx.x;
    if (e >= E) return;
    int dst = edge_at(ei, E + e);
    if ((unsigned)dst < (unsigned)N) atomicAdd(&g_cnt[dst], 1);
}

__global__ void k_scan1(int N) {
    __shared__ int sm[1024];
    int tid = threadIdx.x;
    int i = blockIdx.x * 1024 + tid;
    sm[tid] = (i < N) ? g_cnt[i] : 0;
    __syncthreads();
    for (int off = 1; off < 1024; off <<= 1) {
        int t = (tid >= off) ? sm[tid - off] : 0;
        __syncthreads();
        sm[tid] += t;
        __syncthreads();
    }
    if (i < N) g_scan[i] = sm[tid];
    if (tid == 1023) g_bsum[blockIdx.x] = sm[1023];
}

__global__ void k_scan2(int nb) {
    __shared__ int sm[1024];
    int tid = threadIdx.x;
    sm[tid] = (tid < nb) ? g_bsum[tid] : 0;
    __syncthreads();
    for (int off = 1; off < 1024; off <<= 1) {
        int t = (tid >= off) ? sm[tid - off] : 0;
        __syncthreads();
        sm[tid] += t;
        __syncthreads();
    }
    if (tid < nb) g_bsum[tid] = sm[tid];
}

__global__ void k_scan3(int N) {
    int i = blockIdx.x * 1024 + threadIdx.x;
    if (i >= N) return;
    int pre = (blockIdx.x > 0) ? g_bsum[blockIdx.x - 1] : 0;
    int inc = g_scan[i] + pre;
    g_off[i + 1] = inc;
    g_cur[i] = inc - g_cnt[i];
    if (i == 0) g_off[0] = 0;
}

__global__ void k_scatter(const void* __restrict__ ei, int E, int N) {
    int t = blockIdx.x * blockDim.x + threadIdx.x;
    int src, dst;
    if (t < E) {
        src = edge_at(ei, t);
        dst = edge_at(ei, E + t);
        if ((unsigned)src >= (unsigned)N || (unsigned)dst >= (unsigned)N) return;
    }
    else if (t < E + N) { src = dst = t - E; }
    else return;
    int pos = atomicAdd(&g_cur[dst], 1);
    g_csrc[pos] = src;
}

// ---------------- TF32 tensor-core GEMM ----------------
// BM=128, BN=128, BK=16, 256 threads, 8 warps; warp tile 32x64 (m16n8k8).
// ASEL: 0 = external A, 1 = g_x1, 2 = g_agg.
// MODE 0: C = A@B into g_h, fused attention scores -> g_ss/g_sd.
// MODE 1: Cext = 0.25*acc + bias + g_x2 (layer 3).
// COMP 1: 3-term compensated tf32 (hi/lo split) for ~fp32 accuracy.

__device__ __forceinline__ unsigned f2tf(float f) {
    unsigned u;
    asm("cvt.rna.tf32.f32 %0, %1;" : "=r"(u) : "f"(f));
    return u;
}
__device__ __forceinline__ uint4 cvt4(float4 v) {
    uint4 u;
    u.x = f2tf(v.x); u.y = f2tf(v.y); u.z = f2tf(v.z); u.w = f2tf(v.w);
    return u;
}
__device__ __forceinline__ uint4 cvt4lo(float4 v, uint4 h) {
    uint4 u;
    u.x = f2tf(v.x - __uint_as_float(h.x));
    u.y = f2tf(v.y - __uint_as_float(h.y));
    u.z = f2tf(v.z - __uint_as_float(h.z));
    u.w = f2tf(v.w - __uint_as_float(h.w));
    return u;
}
__device__ __forceinline__ void mma_tf32(float* d, const unsigned* a, const unsigned* b) {
    asm volatile(
        "mma.sync.aligned.m16n8k8.row.col.f32.tf32.tf32.f32 "
        "{%0,%1,%2,%3}, {%4,%5,%6,%7}, {%8,%9}, {%0,%1,%2,%3};\n"
        : "+f"(d[0]), "+f"(d[1]), "+f"(d[2]), "+f"(d[3])
        : "r"(a[0]), "r"(a[1]), "r"(a[2]), "r"(a[3]), "r"(b[0]), "r"(b[1]));
}

#define AS_STRIDE 20
#define BS_STRIDE 136

template <int KDIM, int MODE, int ASEL, int COMP>
__global__ void __launch_bounds__(256, 2)
k_mma(const float* __restrict__ Aext, const float* __restrict__ B,
      float* __restrict__ Cext, const float* __restrict__ bias,
      const float* __restrict__ aS, const float* __restrict__ aD, int M)
{
    const float* A = (ASEL == 0) ? Aext : (ASEL == 1) ? (const float*)g_x1
                                                      : (const float*)g_agg;
    __shared__ unsigned As[128 * AS_STRIDE];
    __shared__ unsigned Bs[16 * BS_STRIDE];
    __shared__ unsigned AsL[COMP ? 128 * AS_STRIDE : 1];
    __shared__ unsigned BsL[COMP ? 16 * BS_STRIDE : 1];
    __shared__ float    sS[MODE == 0 ? 4 * 128 : 1];
    __shared__ float    sD[MODE == 0 ? 4 * 128 : 1];
    __shared__ float    aSm[MODE == 0 ? 256 : 1];

    const int tid = threadIdx.x;
    const int lane = tid & 31;
    const int wid = tid >> 5;
    const int warpM = wid >> 1, warpN = wid & 1;
    const int rowBase = blockIdx.x * 128;

    if (MODE == 0) {               // stage attention vectors (used at epilogue)
        if (tid < 128) aSm[tid] = aS[tid];
        else if (tid < 256) aSm[tid] = aD[tid - 128];
    }

    const int aRow = tid >> 2;
    const int aCol = (tid & 3) * 4;
    const int bRow = tid >> 4;
    const int bCol = (tid & 15) * 4;

    float acc[2][8][4];
    #pragma unroll
    for (int t = 0; t < 2; t++)
        #pragma unroll
        for (int j = 0; j < 8; j++)
            #pragma unroll
            for (int q = 0; q < 4; q++) acc[t][j][q] = 0.f;

    const float4 z4 = make_float4(0.f, 0.f, 0.f, 0.f);
    float4 pa0, pa1, pb0, pb1;

    {   // prefetch k0 = 0
        int r0 = rowBase + aRow;
        pa0 = (r0 < M) ? *(const float4*)&A[(size_t)r0 * KDIM + aCol] : z4;
        int r1 = r0 + 64;
        pa1 = (r1 < M) ? *(const float4*)&A[(size_t)r1 * KDIM + aCol] : z4;
        int j = bRow;
        const float* br = (MODE == 1) ? B + (size_t)(j & 127) * 512 + (size_t)(j >> 7) * 128
                                      : B + (size_t)j * 128;
        pb0 = *(const float4*)&br[bCol];
        pb1 = *(const float4*)&br[bCol + 64];
    }

    for (int k0 = 0; k0 < KDIM; k0 += 16) {
        uint4 h0 = cvt4(pa0), h1 = cvt4(pa1), g0 = cvt4(pb0), g1 = cvt4(pb1);
        *(uint4*)&As[aRow * AS_STRIDE + aCol]        = h0;
        *(uint4*)&As[(aRow + 64) * AS_STRIDE + aCol] = h1;
        *(uint4*)&Bs[bRow * BS_STRIDE + bCol]        = g0;
        *(uint4*)&Bs[bRow * BS_STRIDE + bCol + 64]   = g1;
        if (COMP) {
            *(uint4*)&AsL[aRow * AS_STRIDE + aCol]        = cvt4lo(pa0, h0);
            *(uint4*)&AsL[(aRow + 64) * AS_STRIDE + aCol] = cvt4lo(pa1, h1);
            *(uint4*)&BsL[bRow * BS_STRIDE + bCol]        = cvt4lo(pb0, g0);
            *(uint4*)&BsL[bRow * BS_STRIDE + bCol + 64]   = cvt4lo(pb1, g1);
        }
        __syncthreads();

        if (k0 + 16 < KDIM) {      // prefetch next tile
            int kn = k0 + 16;
            int r0 = rowBase + aRow;
            pa0 = (r0 < M) ? *(const float4*)&A[(size_t)r0 * KDIM + kn + aCol] : z4;
            int r1 = r0 + 64;
            pa1 = (r1 < M) ? *(const float4*)&A[(size_t)r1 * KDIM + kn + aCol] : z4;
            int j = kn + bRow;
            const float* br = (MODE == 1) ? B + (size_t)(j & 127) * 512 + (size_t)(j >> 7) * 128
                                          : B + (size_t)j * 128;
            pb0 = *(const float4*)&br[bCol];
            pb1 = *(const float4*)&br[bCol + 64];
        }

        #pragma unroll
        for (int s = 0; s < 2; s++) {
            const int kc = s * 8;
            unsigned afh[2][4], afl[2][4];
            const int arow = warpM * 32 + (lane >> 2);
            const int acol = kc + (lane & 3);
            #pragma unroll
            for (int t = 0; t < 2; t++) {
                int r = arow + t * 16;
                afh[t][0] = As[r * AS_STRIDE + acol];
                afh[t][1] = As[(r + 8) * AS_STRIDE + acol];
                afh[t][2] = As[r * AS_STRIDE + acol + 4];
                afh[t][3] = As[(r + 8) * AS_STRIDE + acol + 4];
                if (COMP) {
                    afl[t][0] = AsL[r * AS_STRIDE + acol];
                    afl[t][1] = AsL[(r + 8) * AS_STRIDE + acol];
                    afl[t][2] = AsL[r * AS_STRIDE + acol + 4];
                    afl[t][3] = AsL[(r + 8) * AS_STRIDE + acol + 4];
                }
            }
            const int bk = kc + (lane & 3);
            #pragma unroll
            for (int j = 0; j < 8; j++) {
                int bn = warpN * 64 + j * 8 + (lane >> 2);
                unsigned bfh[2], bfl[2];
                bfh[0] = Bs[bk * BS_STRIDE + bn];
                bfh[1] = Bs[(bk + 4) * BS_STRIDE + bn];
                if (COMP) {
                    bfl[0] = BsL[bk * BS_STRIDE + bn];
                    bfl[1] = BsL[(bk + 4) * BS_STRIDE + bn];
                }
                #pragma unroll
                for (int t = 0; t < 2; t++) {
                    mma_tf32(acc[t][j], afh[t], bfh);
                    if (COMP) {
                        mma_tf32(acc[t][j], afl[t], bfh);
                        mma_tf32(acc[t][j], afh[t], bfl);
                    }
                }
            }
        }
        __syncthreads();
    }

    // ---- epilogue: store C ----
    #pragma unroll
    for (int t = 0; t < 2; t++) {
        int r0 = rowBase + warpM * 32 + t * 16 + (lane >> 2);
        int r1 = r0 + 8;
        #pragma unroll
        for (int j = 0; j < 8; j++) {
            int c = warpN * 64 + j * 8 + 2 * (lane & 3);
            if (MODE == 0) {
                *(float2*)&g_h[(size_t)r0 * 128 + c] = make_float2(acc[t][j][0], acc[t][j][1]);
                *(float2*)&g_h[(size_t)r1 * 128 + c] = make_float2(acc[t][j][2], acc[t][j][3]);
            } else {
                if (r0 < M) {
                    float v0 = 0.25f * acc[t][j][0] + bias[c]     + g_x2[(size_t)r0 * 128 + c];
                    float v1 = 0.25f * acc[t][j][1] + bias[c + 1] + g_x2[(size_t)r0 * 128 + c + 1];
                    *(float2*)&Cext[(size_t)r0 * 128 + c] = make_float2(v0, v1);
                }
                if (r1 < M) {
                    float v2 = 0.25f * acc[t][j][2] + bias[c]     + g_x2[(size_t)r1 * 128 + c];
                    float v3 = 0.25f * acc[t][j][3] + bias[c + 1] + g_x2[(size_t)r1 * 128 + c + 1];
                    *(float2*)&Cext[(size_t)r1 * 128 + c] = make_float2(v2, v3);
                }
            }
        }
    }

    // ---- fused attention scores (MODE 0 only) ----
    if (MODE == 0) {
        float ps[2][2][2], pd[2][2][2];
        #pragma unroll
        for (int t = 0; t < 2; t++)
            #pragma unroll
            for (int u = 0; u < 2; u++)
                #pragma unroll
                for (int hs = 0; hs < 2; hs++) { ps[t][u][hs] = 0.f; pd[t][u][hs] = 0.f; }
        #pragma unroll
        for (int t = 0; t < 2; t++)
            #pragma unroll
            for (int j = 0; j < 8; j++) {
                int hs = j >> 2;
                int head = warpN * 2 + hs;
                int cIn = (j & 3) * 8 + 2 * (lane & 3);
                float a0s = aSm[head * 32 + cIn],       a1s = aSm[head * 32 + cIn + 1];
                float a0d = aSm[128 + head * 32 + cIn], a1d = aSm[128 + head * 32 + cIn + 1];
                ps[t][0][hs] += acc[t][j][0] * a0s + acc[t][j][1] * a1s;
                ps[t][1][hs] += acc[t][j][2] * a0s + acc[t][j][3] * a1s;
                pd[t][0][hs] += acc[t][j][0] * a0d + acc[t][j][1] * a1d;
                pd[t][1][hs] += acc[t][j][2] * a0d + acc[t][j][3] * a1d;
            }
        #pragma unroll
        for (int off = 1; off <= 2; off <<= 1)
            #pragma unroll
            for (int t = 0; t < 2; t++)
                #pragma unroll
                for (int u = 0; u < 2; u++)
                    #pragma unroll
                    for (int hs = 0; hs < 2; hs++) {
                        ps[t][u][hs] += __shfl_xor_sync(0xffffffffu, ps[t][u][hs], off);
                        pd[t][u][hs] += __shfl_xor_sync(0xffffffffu, pd[t][u][hs], off);
                    }
        if ((lane & 3) == 0) {
            #pragma unroll
            for (int t = 0; t < 2; t++)
                #pragma unroll
                for (int u = 0; u < 2; u++)
                    #pragma unroll
                    for (int hs = 0; hs < 2; hs++) {
                        int rl = warpM * 32 + t * 16 + u * 8 + (lane >> 2);
                        int head = warpN * 2 + hs;
                        sS[head * 128 + rl] = ps[t][u][hs];
                        sD[head * 128 + rl] = pd[t][u][hs];
                    }
        }
        __syncthreads();
        if (tid < 128) {
            int r = rowBase + tid;
            float4 vs = make_float4(sS[tid], sS[128 + tid], sS[256 + tid], sS[384 + tid]);
            float4 vd = make_float4(sD[tid], sD[128 + tid], sD[256 + tid], sD[384 + tid]);
            *(float4*)&g_ss[4 * r] = vs;
            *(float4*)&g_sd[4 * r] = vd;
        }
    }
}

// ---------------- per-node softmax + aggregate (layers 1/2) -----------------
// warp per node; edge scores cached in registers (deg<=32 fast path), float4
// feature gathers (lane owns features 4*lane..4*lane+3, head = lane>>3).
template <int LAYER>
__global__ void k_agg(const float* __restrict__ xext,
                      const float* __restrict__ bias, int N)
{
    const float* xin = (LAYER == 1) ? xext : (const float*)g_x1;
    float* xout = (LAYER == 1) ? (float*)g_x1 : (float*)g_x2;

    int warp = (blockIdx.x * blockDim.x + threadIdx.x) >> 5;
    if (warp >= N) return;
    int lane = threadIdx.x & 31;
    int beg = g_off[warp], end = g_off[warp + 1];
    int deg = end - beg;

    float4 sdv = *(const float4*)(g_sd + 4 * warp);
    float e0 = -1e30f, e1 = -1e30f, e2 = -1e30f, e3 = -1e30f;
    int sl = 0;
    if (lane < deg) {
        sl = g_csrc[beg + lane];
        float4 sv = *(const float4*)(g_ss + 4 * sl);
        e0 = lrelu(sv.x + sdv.x); e1 = lrelu(sv.y + sdv.y);
        e2 = lrelu(sv.z + sdv.z); e3 = lrelu(sv.w + sdv.w);
    }
    float m0 = e0, m1 = e1, m2 = e2, m3 = e3;
    for (int i = beg + 32 + lane; i < end; i += 32) {   // rare: deg > 32
        int s = g_csrc[i];
        float4 sv = *(const float4*)(g_ss + 4 * s);
        m0 = fmaxf(m0, lrelu(sv.x + sdv.x)); m1 = fmaxf(m1, lrelu(sv.y + sdv.y));
        m2 = fmaxf(m2, lrelu(sv.z + sdv.z)); m3 = fmaxf(m3, lrelu(sv.w + sdv.w));
    }
    #pragma unroll
    for (int o = 16; o > 0; o >>= 1) {
        m0 = fmaxf(m0, __shfl_xor_sync(0xffffffffu, m0, o));
        m1 = fmaxf(m1, __shfl_xor_sync(0xffffffffu, m1, o));
        m2 = fmaxf(m2, __shfl_xor_sync(0xffffffffu, m2, o));
        m3 = fmaxf(m3, __shfl_xor_sync(0xffffffffu, m3, o));
    }

    int hsel = lane >> 3;
    float4 vacc = make_float4(0.f, 0.f, 0.f, 0.f);
    float z0 = 0.f, z1 = 0.f, z2 = 0.f, z3 = 0.f;
    int nf = deg < 32 ? deg : 32;
    for (int i = 0; i < nf; i++) {
        float q0 = __shfl_sync(0xffffffffu, e0, i);
        float q1 = __shfl_sync(0xffffffffu, e1, i);
        float q2 = __shfl_sync(0xffffffffu, e2, i);
        float q3 = __shfl_sync(0xffffffffu, e3, i);
        int s = __shfl_sync(0xffffffffu, sl, i);
        float p0 = __expf(q0 - m0), p1 = __expf(q1 - m1);
        float p2 = __expf(q2 - m2), p3 = __expf(q3 - m3);
        z0 += p0; z1 += p1; z2 += p2; z3 += p3;
        float ph = (hsel == 0) ? p0 : (hsel == 1) ? p1 : (hsel == 2) ? p2 : p3;
        float4 row = *(const float4*)&g_h[(size_t)s * 128 + 4 * lane];
        vacc.x += ph * row.x; vacc.y += ph * row.y;
        vacc.z += ph * row.z; vacc.w += ph * row.w;
    }
    for (int i = beg + 32; i < end; i++) {              // rare tail
        int s = g_csrc[i];
        float4 sv = *(const float4*)(g_ss + 4 * s);
        float p0 = __expf(lrelu(sv.x + sdv.x) - m0), p1 = __expf(lrelu(sv.y + sdv.y) - m1);
        float p2 = __expf(lrelu(sv.z + sdv.z) - m2), p3 = __expf(lrelu(sv.w + sdv.w) - m3);
        z0 += p0; z1 += p1; z2 += p2; z3 += p3;
        float ph = (hsel == 0) ? p0 : (hsel == 1) ? p1 : (hsel == 2) ? p2 : p3;
        float4 row = *(const float4*)&g_h[(size_t)s * 128 + 4 * lane];
        vacc.x += ph * row.x; vacc.y += ph * row.y;
        vacc.z += ph * row.z; vacc.w += ph * row.w;
    }

    float zh = (hsel == 0) ? z0 : (hsel == 1) ? z1 : (hsel == 2) ? z2 : z3;
    float inv = 1.f / (zh + 1e-16f);
    int f = 4 * lane;
    float4 bi = *(const float4*)&bias[f];
    float4 xi = *(const float4*)&xin[(size_t)warp * 128 + f];
    float4 v;
    v.x = vacc.x * inv + bi.x + xi.x;  v.x = v.x > 0.f ? v.x : expm1f(v.x);
    v.y = vacc.y * inv + bi.y + xi.y;  v.y = v.y > 0.f ? v.y : expm1f(v.y);
    v.z = vacc.z * inv + bi.z + xi.z;  v.z = v.z > 0.f ? v.z : expm1f(v.z);
    v.w = vacc.w * inv + bi.w + xi.w;  v.w = v.w > 0.f ? v.w : expm1f(v.w);
    *(float4*)&xout[(size_t)warp * 128 + f] = v;
}

// ---------------- layer-3 small weights: ws[k,h] = sum_f W3[k,h*128+f]*a[h,f]
__global__ void k_wsmall(const float* __restrict__ W3, const float* __restrict__ as3,
                         const float* __restrict__ ad3)
{
    int t = blockIdx.x * blockDim.x + threadIdx.x;
    if (t >= 1024) return;
    int which = t >> 9;
    int idx = t & 511;
    int k = idx >> 2, hh = idx & 3;
    const float* a = which ? ad3 : as3;
    const float* wrow = W3 + (size_t)k * 512 + hh * 128;
    float s = 0.f;
    for (int f = 0; f < 128; f++) s += wrow[f] * a[hh * 128 + f];
    if (which) g_wd[k * 4 + hh] = s; else g_ws[k * 4 + hh] = s;
}

// ---------------- layer-3 scores: s = x2 @ ws / wd ----------------
__global__ void k_scores3(int N)
{
    int warp = (blockIdx.x * blockDim.x + threadIdx.x) >> 5;
    if (warp >= N) return;
    int lane = threadIdx.x & 31;
    const float* xr = g_x2 + (size_t)warp * 128;
    float ps[4] = {0.f, 0.f, 0.f, 0.f}, pd[4] = {0.f, 0.f, 0.f, 0.f};
    #pragma unroll
    for (int kk = 0; kk < 4; kk++) {
        int k = kk * 32 + lane;
        float xv = xr[k];
        #pragma unroll
        for (int hh = 0; hh < 4; hh++) {
            ps[hh] += xv * g_ws[k * 4 + hh];
            pd[hh] += xv * g_wd[k * 4 + hh];
        }
    }
    #pragma unroll
    for (int o = 16; o > 0; o >>= 1)
        #pragma unroll
        for (int hh = 0; hh < 4; hh++) {
            ps[hh] += __shfl_xor_sync(0xffffffffu, ps[hh], o);
            pd[hh] += __shfl_xor_sync(0xffffffffu, pd[hh], o);
        }
    if (lane == 0) {
        #pragma unroll
        for (int hh = 0; hh < 4; hh++) {
            g_ss[warp * 4 + hh] = ps[hh];
            g_sd[warp * 4 + hh] = pd[hh];
        }
    }
}

// ---------------- layer-3 aggregate: agg[n,h*128+k] = sum_e alpha_h x2[src,k]
__global__ void k_agg3(int N)
{
    int warp = (blockIdx.x * blockDim.x + threadIdx.x) >> 5;
    if (warp >= N) return;
    int lane = threadIdx.x & 31;
    int beg = g_off[warp], end = g_off[warp + 1];
    int deg = end - beg;

    float4 sdv = *(const float4*)(g_sd + 4 * warp);
    float e0 = -1e30f, e1 = -1e30f, e2 = -1e30f, e3 = -1e30f;
    int sl = 0;
    if (lane < deg) {
        sl = g_csrc[beg + lane];
        float4 sv = *(const float4*)(g_ss + 4 * sl);
        e0 = lrelu(sv.x + sdv.x); e1 = lrelu(sv.y + sdv.y);
        e2 = lrelu(sv.z + sdv.z); e3 = lrelu(sv.w + sdv.w);
    }
    float m0 = e0, m1 = e1, m2 = e2, m3 = e3;
    for (int i = beg + 32 + lane; i < end; i += 32) {
        int s = g_csrc[i];
        float4 sv = *(const float4*)(g_ss + 4 * s);
        m0 = fmaxf(m0, lrelu(sv.x + sdv.x)); m1 = fmaxf(m1, lrelu(sv.y + sdv.y));
        m2 = fmaxf(m2, lrelu(sv.z + sdv.z)); m3 = fmaxf(m3, lrelu(sv.w + sdv.w));
    }
    #pragma unroll
    for (int o = 16; o > 0; o >>= 1) {
        m0 = fmaxf(m0, __shfl_xor_sync(0xffffffffu, m0, o));
        m1 = fmaxf(m1, __shfl_xor_sync(0xffffffffu, m1, o));
        m2 = fmaxf(m2, __shfl_xor_sync(0xffffffffu, m2, o));
        m3 = fmaxf(m3, __shfl_xor_sync(0xffffffffu, m3, o));
    }

    float4 va0 = make_float4(0,0,0,0), va1 = va0, va2 = va0, va3 = va0;
    float z0 = 0.f, z1 = 0.f, z2 = 0.f, z3 = 0.f;
    int nf = deg < 32 ? deg : 32;
    for (int i = 0; i < nf; i++) {
        float q0 = __shfl_sync(0xffffffffu, e0, i);
        float q1 = __shfl_sync(0xffffffffu, e1, i);
        float q2 = __shfl_sync(0xffffffffu, e2, i);
        float q3 = __shfl_sync(0xffffffffu, e3, i);
        int s = __shfl_sync(0xffffffffu, sl, i);
        float p0 = __expf(q0 - m0), p1 = __expf(q1 - m1);
        float p2 = __expf(q2 - m2), p3 = __expf(q3 - m3);
        z0 += p0; z1 += p1; z2 += p2; z3 += p3;
        float4 row = *(const float4*)&g_x2[(size_t)s * 128 + 4 * lane];
        va0.x += p0*row.x; va0.y += p0*row.y; va0.z += p0*row.z; va0.w += p0*row.w;
        va1.x += p1*row.x; va1.y += p1*row.y; va1.z += p1*row.z; va1.w += p1*row.w;
        va2.x += p2*row.x; va2.y += p2*row.y; va2.z += p2*row.z; va2.w += p2*row.w;
        va3.x += p3*row.x; va3.y += p3*row.y; va3.z += p3*row.z; va3.w += p3*row.w;
    }
    for (int i = beg + 32; i < end; i++) {
        int s = g_csrc[i];
        float4 sv = *(const float4*)(g_ss + 4 * s);
        float p0 = __expf(lrelu(sv.x + sdv.x) - m0), p1 = __expf(lrelu(sv.y + sdv.y) - m1);
        float p2 = __expf(lrelu(sv.z + sdv.z) - m2), p3 = __expf(lrelu(sv.w + sdv.w) - m3);
        z0 += p0; z1 += p1; z2 += p2; z3 += p3;
        float4 row = *(const float4*)&g_x2[(size_t)s * 128 + 4 * lane];
        va0.x += p0*row.x; va0.y += p0*row.y; va0.z += p0*row.z; va0.w += p0*row.w;
        va1.x += p1*row.x; va1.y += p1*row.y; va1.z += p1*row.z; va1.w += p1*row.w;
        va2.x += p2*row.x; va2.y += p2*row.y; va2.z += p2*row.z; va2.w += p2*row.w;
        va3.x += p3*row.x; va3.y += p3*row.y; va3.z += p3*row.z; va3.w += p3*row.w;
    }

    float i0 = 1.f/(z0+1e-16f), i1 = 1.f/(z1+1e-16f), i2 = 1.f/(z2+1e-16f), i3 = 1.f/(z3+1e-16f);
    size_t base = (size_t)warp * 512 + 4 * lane;
    *(float4*)&g_agg[base]       = make_float4(va0.x*i0, va0.y*i0, va0.z*i0, va0.w*i0);
    *(float4*)&g_agg[base + 128] = make_float4(va1.x*i1, va1.y*i1, va1.z*i1, va1.w*i1);
    *(float4*)&g_agg[base + 256] = make_float4(va2.x*i2, va2.y*i2, va2.z*i2, va2.w*i2);
    *(float4*)&g_agg[base + 384] = make_float4(va3.x*i3, va3.y*i3, va3.z*i3, va3.w*i3);
}

// ---------------- host entry ----------------
extern "C" void kernel_launch(void* const* d_in, const int* in_sizes, int n_in,
                              void* d_out, int out_size)
{
    const float* x   = (const float*)d_in[0];
    const void*  ei  = d_in[1];
    const float* W1  = (const float*)d_in[2];
    const float* as1 = (const float*)d_in[3];
    const float* ad1 = (const float*)d_in[4];
    const float* b1  = (const float*)d_in[5];
    const float* W2  = (const float*)d_in[6];
    const float* as2 = (const float*)d_in[7];
    const float* ad2 = (const float*)d_in[8];
    const float* b2  = (const float*)d_in[9];
    const float* W3  = (const float*)d_in[10];
    const float* as3 = (const float*)d_in[11];
    const float* ad3 = (const float*)d_in[12];
    const float* b3  = (const float*)d_in[13];

    int N = in_sizes[0] / 128;
    int E = in_sizes[1] / 2;

    int nb = (N + 1023) / 1024;
    int nsamp = (2 * E < 8192) ? 2 * E : 8192;

    // edge dtype detect + CSR build
    k_detect<<<1, 512>>>((const int*)ei, nsamp);
    k_init_cnt<<<nb, 1024>>>(N);
    k_hist<<<(E + 255) / 256, 256>>>(ei, E, N);
    k_scan1<<<nb, 1024>>>(N);
    k_scan2<<<1, 1024>>>(nb);
    k_scan3<<<nb, 1024>>>(N);
    k_scatter<<<(E + N + 255) / 256, 256>>>(ei, E, N);

    int gemmBlocks = (N + 127) / 128;
    int aggBlocks  = (N + 7) / 8;   // 8 warps (nodes) per 256-thread block

    // layer 1 (compensated tf32 + fused scores)
    k_mma<128, 0, 0, 1><<<gemmBlocks, 256>>>(x, W1, nullptr, nullptr, as1, ad1, N);
    k_agg<1><<<aggBlocks, 256>>>(x, b1, N);

    // layer 2
    k_mma<128, 0, 1, 1><<<gemmBlocks, 256>>>(nullptr, W2, nullptr, nullptr, as2, ad2, N);
    k_agg<2><<<aggBlocks, 256>>>(nullptr, b2, N);

    // layer 3 (never materializes h3 = [N,4,128])
    k_wsmall<<<4, 256>>>(W3, as3, ad3);
    k_scores3<<<aggBlocks, 256>>>(N);
    k_agg3<<<aggBlocks, 256>>>(N);
    k_mma<512, 1, 2, 0><<<gemmBlocks, 256>>>(nullptr, W3, (float*)d_out, b3, nullptr, nullptr, N);
}

// round 8
// speedup vs baseline: 1.0412x; 1.0412x over previous
#include <cuda_runtime.h>
#include <math.h>

// Problem caps (N=100000, E=800000 per setup_inputs; small safety margin)
#define NCAP 100352
#define ECAP 802816
#define ETCAP (ECAP + NCAP)

// R8 = resubmission of R7 (GPU acquisition timed out; kernel never ran).

// ---------------- device scratch (static, no allocation) ----------------
__device__ float g_h  [(size_t)NCAP * 128];   // per-layer transformed features
__device__ float g_x1 [(size_t)NCAP * 128];   // layer-1 output
__device__ float g_x2 [(size_t)NCAP * 128];   // layer-2 output
__device__ float g_agg[(size_t)NCAP * 512];   // layer-3 weighted x2 aggregate
__device__ float g_ss [NCAP * 4];             // s_src per node/head
__device__ float g_sd [NCAP * 4];             // s_dst per node/head
__device__ int   g_cnt [NCAP];
__device__ int   g_scan[NCAP];
__device__ int   g_bsum[1024];
__device__ int   g_off [NCAP + 1];
__device__ int   g_cur [NCAP];
__device__ int   g_csrc[ETCAP];
__device__ float g_ws[128 * 4];               // W3_h @ a_src3_h
__device__ float g_wd[128 * 4];               // W3_h @ a_dst3_h
__device__ int   g_i64;                       // 1 if edge_index is int64, 0 if int32

__device__ __forceinline__ float lrelu(float e) { return e > 0.f ? e : 0.2f * e; }

__device__ __forceinline__ int edge_at(const void* ei, int idx) {
    if (g_i64) return (int)((const long long*)ei)[idx];
    return ((const int*)ei)[idx];
}

// ---------------- edge dtype detection ----------------
__global__ void k_detect(const int* __restrict__ ei32, int nsamp) {
    __shared__ int any;
    if (threadIdx.x == 0) any = 0;
    __syncthreads();
    for (int i = threadIdx.x * 2 + 1; i < nsamp; i += 512)
        if (ei32[i] != 0) { any = 1; break; }
    __syncthreads();
    if (threadIdx.x == 0) g_i64 = any ? 0 : 1;
}

// ---------------- CSR build ----------------
__global__ void k_init_cnt(int N) {
    int i = blockIdx.x * blockDim.x + threadIdx.x;
    if (i < N) g_cnt[i] = 1;   // self loop
}

__global__ void k_hist(const void* __restrict__ ei, int E, int N) {
    int e = blockIdx.x * blockDim.x + threadIdx.x;
    if (e >= E) return;
    int dst = edge_at(ei, E + e);
    if ((unsigned)dst < (unsigned)N) atomicAdd(&g_cnt[dst], 1);
}

__global__ void k_scan1(int N) {
    __shared__ int sm[1024];
    int tid = threadIdx.x;
    int i = blockIdx.x * 1024 + tid;
    sm[tid] = (i < N) ? g_cnt[i] : 0;
    __syncthreads();
    for (int off = 1; off < 1024; off <<= 1) {
        int t = (tid >= off) ? sm[tid - off] : 0;
        __syncthreads();
        sm[tid] += t;
        __syncthreads();
    }
    if (i < N) g_scan[i] = sm[tid];
    if (tid == 1023) g_bsum[blockIdx.x] = sm[1023];
}

__global__ void k_scan2(int nb) {
    __shared__ int sm[1024];
    int tid = threadIdx.x;
    sm[tid] = (tid < nb) ? g_bsum[tid] : 0;
    __syncthreads();
    for (int off = 1; off < 1024; off <<= 1) {
        int t = (tid >= off) ? sm[tid - off] : 0;
        __syncthreads();
        sm[tid] += t;
        __syncthreads();
    }
    if (tid < nb) g_bsum[tid] = sm[tid];
}

__global__ void k_scan3(int N) {
    int i = blockIdx.x * 1024 + threadIdx.x;
    if (i >= N) return;
    int pre = (blockIdx.x > 0) ? g_bsum[blockIdx.x - 1] : 0;
    int inc = g_scan[i] + pre;
    g_off[i + 1] = inc;
    g_cur[i] = inc - g_cnt[i];
    if (i == 0) g_off[0] = 0;
}

__global__ void k_scatter(const void* __restrict__ ei, int E, int N) {
    int t = blockIdx.x * blockDim.x + threadIdx.x;
    int src, dst;
    if (t < E) {
        src = edge_at(ei, t);
        dst = edge_at(ei, E + t);
        if ((unsigned)src >= (unsigned)N || (unsigned)dst >= (unsigned)N) return;
    }
    else if (t < E + N) { src = dst = t - E; }
    else return;
    int pos = atomicAdd(&g_cur[dst], 1);
    g_csrc[pos] = src;
}

// ---------------- MMA helpers ----------------
__device__ __forceinline__ unsigned f2tf(float f) {
    unsigned u;
    asm("cvt.rna.tf32.f32 %0, %1;" : "=r"(u) : "f"(f));
    return u;
}
__device__ __forceinline__ uint4 cvt4(float4 v) {
    uint4 u;
    u.x = f2tf(v.x); u.y = f2tf(v.y); u.z = f2tf(v.z); u.w = f2tf(v.w);
    return u;
}
__device__ __forceinline__ void mma_tf32(float* d, const unsigned* a, const unsigned* b) {
    asm volatile(
        "mma.sync.aligned.m16n8k8.row.col.f32.tf32.tf32.f32 "
        "{%0,%1,%2,%3}, {%4,%5,%6,%7}, {%8,%9}, {%0,%1,%2,%3};\n"
        : "+f"(d[0]), "+f"(d[1]), "+f"(d[2]), "+f"(d[3])
        : "r"(a[0]), "r"(a[1]), "r"(a[2]), "r"(a[3]), "r"(b[0]), "r"(b[1]));
}
__device__ __forceinline__ void mma_bf16(float* d, const unsigned* a, const unsigned* b) {
    asm volatile(
        "mma.sync.aligned.m16n8k16.row.col.f32.bf16.bf16.f32 "
        "{%0,%1,%2,%3}, {%4,%5,%6,%7}, {%8,%9}, {%0,%1,%2,%3};\n"
        : "+f"(d[0]), "+f"(d[1]), "+f"(d[2]), "+f"(d[3])
        : "r"(a[0]), "r"(a[1]), "r"(a[2]), "r"(a[3]), "r"(b[0]), "r"(b[1]));
}
// pack (k even -> low half, k odd -> high half)
__device__ __forceinline__ unsigned packbf(float e, float o) {
    unsigned r;
    asm("cvt.rn.bf16x2.f32 %0, %1, %2;" : "=r"(r) : "f"(o), "f"(e));
    return r;
}
__device__ __forceinline__ float lo_f(unsigned w) { return __uint_as_float(w << 16); }
__device__ __forceinline__ float hi_f(unsigned w) { return __uint_as_float(w & 0xffff0000u); }

// ============ GEMM layers 1/2: bf16x2 3-term split, fused scores ============
// BM=BN=128, K=128, 256 threads, 8 warps, warp tile 32x64 via m16n8k16.
// C (= h) -> g_h, attention scores -> g_ss/g_sd. ASEL 0 = external x, 1 = g_x1.
#define W20 20

template <int ASEL>
__global__ void __launch_bounds__(256, 2)
k_gemm12(const float* __restrict__ Aext, const float* __restrict__ B,
         const float* __restrict__ aS, const float* __restrict__ aD, int M)
{
    const float* A = (ASEL == 0) ? Aext : (const float*)g_x1;
    __shared__ unsigned Ah[128 * W20], Al[128 * W20];
    __shared__ unsigned Bh[128 * W20], Bl[128 * W20];
    __shared__ float sS[512], sD[512], aSm[256];

    const int tid = threadIdx.x;
    const int lane = tid & 31;
    const int wid = tid >> 5;
    const int warpM = wid >> 1, warpN = wid & 1;
    const int rowBase = blockIdx.x * 128;

    if (tid < 128) aSm[tid] = aS[tid];
    else           aSm[tid] = aD[tid - 128];

    const int aRow  = tid >> 2;          // 0..63 (+64 second half)
    const int aColF = (tid & 3) * 4;     // float k base
    const int aColW = (tid & 3) * 2;     // word base
    const int bKp   = tid & 7;           // k-pair 0..7
    const int bCg   = (tid >> 3) * 4;    // column group base 0..124

    float acc[2][8][4];
    #pragma unroll
    for (int t = 0; t < 2; t++)
        #pragma unroll
        for (int j = 0; j < 8; j++)
            #pragma unroll
            for (int q = 0; q < 4; q++) acc[t][j][q] = 0.f;

    const float4 z4 = make_float4(0.f, 0.f, 0.f, 0.f);
    float4 pa0, pa1, pb0, pb1;

    {   // prefetch k0 = 0
        int r0 = rowBase + aRow;
        pa0 = (r0 < M) ? *(const float4*)&A[(size_t)r0 * 128 + aColF] : z4;
        int r1 = r0 + 64;
        pa1 = (r1 < M) ? *(const float4*)&A[(size_t)r1 * 128 + aColF] : z4;
        int j0 = 2 * bKp;
        pb0 = *(const float4*)&B[(size_t)j0 * 128 + bCg];
        pb1 = *(const float4*)&B[(size_t)(j0 + 1) * 128 + bCg];
    }

    for (int k0 = 0; k0 < 128; k0 += 16) {
        // ---- pack + store A (hi/lo) ----
        {
            unsigned h0 = packbf(pa0.x, pa0.y), h1 = packbf(pa0.z, pa0.w);
            Ah[aRow * W20 + aColW]     = h0;
            Ah[aRow * W20 + aColW + 1] = h1;
            Al[aRow * W20 + aColW]     = packbf(pa0.x - lo_f(h0), pa0.y - hi_f(h0));
            Al[aRow * W20 + aColW + 1] = packbf(pa0.z - lo_f(h1), pa0.w - hi_f(h1));
            unsigned g0 = packbf(pa1.x, pa1.y), g1 = packbf(pa1.z, pa1.w);
            Ah[(aRow + 64) * W20 + aColW]     = g0;
            Ah[(aRow + 64) * W20 + aColW + 1] = g1;
            Al[(aRow + 64) * W20 + aColW]     = packbf(pa1.x - lo_f(g0), pa1.y - hi_f(g0));
            Al[(aRow + 64) * W20 + aColW + 1] = packbf(pa1.z - lo_f(g1), pa1.w - hi_f(g1));
        }
        // ---- pack + store B (hi/lo): word = (k even, k odd) for column n ----
        {
            float pe[4] = {pb0.x, pb0.y, pb0.z, pb0.w};
            float po[4] = {pb1.x, pb1.y, pb1.z, pb1.w};
            #pragma unroll
            for (int c = 0; c < 4; c++) {
                unsigned h = packbf(pe[c], po[c]);
                Bh[(bCg + c) * W20 + bKp] = h;
                Bl[(bCg + c) * W20 + bKp] = packbf(pe[c] - lo_f(h), po[c] - hi_f(h));
            }
        }
        __syncthreads();

        if (k0 + 16 < 128) {   // prefetch next slab
            int kn = k0 + 16;
            int r0 = rowBase + aRow;
            pa0 = (r0 < M) ? *(const float4*)&A[(size_t)r0 * 128 + kn + aColF] : z4;
            int r1 = r0 + 64;
            pa1 = (r1 < M) ? *(const float4*)&A[(size_t)r1 * 128 + kn + aColF] : z4;
            int j0 = kn + 2 * bKp;
            pb0 = *(const float4*)&B[(size_t)j0 * 128 + bCg];
            pb1 = *(const float4*)&B[(size_t)(j0 + 1) * 128 + bCg];
        }

        // ---- compute: 3-term bf16 split ----
        {
            const int ar = warpM * 32 + (lane >> 2);
            const int w = lane & 3;
            unsigned ah[2][4], al[2][4];
            #pragma unroll
            for (int t = 0; t < 2; t++) {
                int r = ar + t * 16;
                ah[t][0] = Ah[r * W20 + w];       ah[t][1] = Ah[(r + 8) * W20 + w];
                ah[t][2] = Ah[r * W20 + 4 + w];   ah[t][3] = Ah[(r + 8) * W20 + 4 + w];
                al[t][0] = Al[r * W20 + w];       al[t][1] = Al[(r + 8) * W20 + w];
                al[t][2] = Al[r * W20 + 4 + w];   al[t][3] = Al[(r + 8) * W20 + 4 + w];
            }
            #pragma unroll
            for (int j = 0; j < 8; j++) {
                int n = warpN * 64 + j * 8 + (lane >> 2);
                unsigned bh[2], bl[2];
                bh[0] = Bh[n * W20 + w];  bh[1] = Bh[n * W20 + 4 + w];
                bl[0] = Bl[n * W20 + w];  bl[1] = Bl[n * W20 + 4 + w];
                #pragma unroll
                for (int t = 0; t < 2; t++) {
                    mma_bf16(acc[t][j], ah[t], bh);
                    mma_bf16(acc[t][j], al[t], bh);
                    mma_bf16(acc[t][j], ah[t], bl);
                }
            }
        }
        __syncthreads();
    }

    // ---- store h ----
    #pragma unroll
    for (int t = 0; t < 2; t++) {
        int r0 = rowBase + warpM * 32 + t * 16 + (lane >> 2);
        int r1 = r0 + 8;
        #pragma unroll
        for (int j = 0; j < 8; j++) {
            int c = warpN * 64 + j * 8 + 2 * (lane & 3);
            *(float2*)&g_h[(size_t)r0 * 128 + c] = make_float2(acc[t][j][0], acc[t][j][1]);
            *(float2*)&g_h[(size_t)r1 * 128 + c] = make_float2(acc[t][j][2], acc[t][j][3]);
        }
    }

    // ---- fused attention scores ----
    {
        float ps[2][2][2], pd[2][2][2];
        #pragma unroll
        for (int t = 0; t < 2; t++)
            #pragma unroll
            for (int u = 0; u < 2; u++)
                #pragma unroll
                for (int hs = 0; hs < 2; hs++) { ps[t][u][hs] = 0.f; pd[t][u][hs] = 0.f; }
        #pragma unroll
        for (int t = 0; t < 2; t++)
            #pragma unroll
            for (int j = 0; j < 8; j++) {
                int hs = j >> 2;
                int head = warpN * 2 + hs;
                int cIn = (j & 3) * 8 + 2 * (lane & 3);
                float a0s = aSm[head * 32 + cIn],       a1s = aSm[head * 32 + cIn + 1];
                float a0d = aSm[128 + head * 32 + cIn], a1d = aSm[128 + head * 32 + cIn + 1];
                ps[t][0][hs] += acc[t][j][0] * a0s + acc[t][j][1] * a1s;
                ps[t][1][hs] += acc[t][j][2] * a0s + acc[t][j][3] * a1s;
                pd[t][0][hs] += acc[t][j][0] * a0d + acc[t][j][1] * a1d;
                pd[t][1][hs] += acc[t][j][2] * a0d + acc[t][j][3] * a1d;
            }
        #pragma unroll
        for (int off = 1; off <= 2; off <<= 1)
            #pragma unroll
            for (int t = 0; t < 2; t++)
                #pragma unroll
                for (int u = 0; u < 2; u++)
                    #pragma unroll
                    for (int hs = 0; hs < 2; hs++) {
                        ps[t][u][hs] += __shfl_xor_sync(0xffffffffu, ps[t][u][hs], off);
                        pd[t][u][hs] += __shfl_xor_sync(0xffffffffu, pd[t][u][hs], off);
                    }
        if ((lane & 3) == 0) {
            #pragma unroll
            for (int t = 0; t < 2; t++)
                #pragma unroll
                for (int u = 0; u < 2; u++)
                    #pragma unroll
                    for (int hs = 0; hs < 2; hs++) {
                        int rl = warpM * 32 + t * 16 + u * 8 + (lane >> 2);
                        int head = warpN * 2 + hs;
                        sS[head * 128 + rl] = ps[t][u][hs];
                        sD[head * 128 + rl] = pd[t][u][hs];
                    }
        }
        __syncthreads();
        if (tid < 128) {
            int r = rowBase + tid;
            float4 vs = make_float4(sS[tid], sS[128 + tid], sS[256 + tid], sS[384 + tid]);
            float4 vd = make_float4(sD[tid], sD[128 + tid], sD[256 + tid], sD[384 + tid]);
            *(float4*)&g_ss[4 * r] = vs;
            *(float4*)&g_sd[4 * r] = vd;
        }
    }
}

// ============ GEMM layer 3: single tf32, K=512, fused epilogue ============
#define AS_STRIDE 20
#define BS_STRIDE 136

__global__ void __launch_bounds__(256, 2)
k_gemm3(const float* __restrict__ B, float* __restrict__ Cext,
        const float* __restrict__ bias, int M)
{
    const float* A = (const float*)g_agg;
    __shared__ unsigned As[128 * AS_STRIDE];
    __shared__ unsigned Bs[16 * BS_STRIDE];

    const int tid = threadIdx.x;
    const int lane = tid & 31;
    const int wid = tid >> 5;
    const int warpM = wid >> 1, warpN = wid & 1;
    const int rowBase = blockIdx.x * 128;

    const int aRow = tid >> 2;
    const int aCol = (tid & 3) * 4;
    const int bRow = tid >> 4;
    const int bCol = (tid & 15) * 4;

    float acc[2][8][4];
    #pragma unroll
    for (int t = 0; t < 2; t++)
        #pragma unroll
        for (int j = 0; j < 8; j++)
            #pragma unroll
            for (int q = 0; q < 4; q++) acc[t][j][q] = 0.f;

    const float4 z4 = make_float4(0.f, 0.f, 0.f, 0.f);
    float4 pa0, pa1, pb0, pb1;

    {   // prefetch k0 = 0
        int r0 = rowBase + aRow;
        pa0 = (r0 < M) ? *(const float4*)&A[(size_t)r0 * 512 + aCol] : z4;
        int r1 = r0 + 64;
        pa1 = (r1 < M) ? *(const float4*)&A[(size_t)r1 * 512 + aCol] : z4;
        int j = bRow;
        const float* br = B + (size_t)(j & 127) * 512 + (size_t)(j >> 7) * 128;
        pb0 = *(const float4*)&br[bCol];
        pb1 = *(const float4*)&br[bCol + 64];
    }

    for (int k0 = 0; k0 < 512; k0 += 16) {
        *(uint4*)&As[aRow * AS_STRIDE + aCol]        = cvt4(pa0);
        *(uint4*)&As[(aRow + 64) * AS_STRIDE + aCol] = cvt4(pa1);
        *(uint4*)&Bs[bRow * BS_STRIDE + bCol]        = cvt4(pb0);
        *(uint4*)&Bs[bRow * BS_STRIDE + bCol + 64]   = cvt4(pb1);
        __syncthreads();

        if (k0 + 16 < 512) {
            int kn = k0 + 16;
            int r0 = rowBase + aRow;
            pa0 = (r0 < M) ? *(const float4*)&A[(size_t)r0 * 512 + kn + aCol] : z4;
            int r1 = r0 + 64;
            pa1 = (r1 < M) ? *(const float4*)&A[(size_t)r1 * 512 + kn + aCol] : z4;
            int j = kn + bRow;
            const float* br = B + (size_t)(j & 127) * 512 + (size_t)(j >> 7) * 128;
            pb0 = *(const float4*)&br[bCol];
            pb1 = *(const float4*)&br[bCol + 64];
        }

        #pragma unroll
        for (int s = 0; s < 2; s++) {
            const int kc = s * 8;
            unsigned af[2][4];
            const int arow = warpM * 32 + (lane >> 2);
            const int acol = kc + (lane & 3);
            #pragma unroll
            for (int t = 0; t < 2; t++) {
                int r = arow + t * 16;
                af[t][0] = As[r * AS_STRIDE + acol];
                af[t][1] = As[(r + 8) * AS_STRIDE + acol];
                af[t][2] = As[r * AS_STRIDE + acol + 4];
                af[t][3] = As[(r + 8) * AS_STRIDE + acol + 4];
            }
            const int bk = kc + (lane & 3);
            #pragma unroll
            for (int j = 0; j < 8; j++) {
                int bn = warpN * 64 + j * 8 + (lane >> 2);
                unsigned bf[2];
                bf[0] = Bs[bk * BS_STRIDE + bn];
                bf[1] = Bs[(bk + 4) * BS_STRIDE + bn];
                #pragma unroll
                for (int t = 0; t < 2; t++)
                    mma_tf32(acc[t][j], af[t], bf);
            }
        }
        __syncthreads();
    }

    #pragma unroll
    for (int t = 0; t < 2; t++) {
        int r0 = rowBase + warpM * 32 + t * 16 + (lane >> 2);
        int r1 = r0 + 8;
        #pragma unroll
        for (int j = 0; j < 8; j++) {
            int c = warpN * 64 + j * 8 + 2 * (lane & 3);
            if (r0 < M) {
                float v0 = 0.25f * acc[t][j][0] + bias[c]     + g_x2[(size_t)r0 * 128 + c];
                float v1 = 0.25f * acc[t][j][1] + bias[c + 1] + g_x2[(size_t)r0 * 128 + c + 1];
                *(float2*)&Cext[(size_t)r0 * 128 + c] = make_float2(v0, v1);
            }
            if (r1 < M) {
                float v2 = 0.25f * acc[t][j][2] + bias[c]     + g_x2[(size_t)r1 * 128 + c];
                float v3 = 0.25f * acc[t][j][3] + bias[c + 1] + g_x2[(size_t)r1 * 128 + c + 1];
                *(float2*)&Cext[(size_t)r1 * 128 + c] = make_float2(v2, v3);
            }
        }
    }
}

// ---------------- per-node softmax + aggregate (layers 1/2) -----------------
template <int LAYER>
__global__ void k_agg(const float* __restrict__ xext,
                      const float* __restrict__ bias, int N)
{
    const float* xin = (LAYER == 1) ? xext : (const float*)g_x1;
    float* xout = (LAYER == 1) ? (float*)g_x1 : (float*)g_x2;

    int warp = (blockIdx.x * blockDim.x + threadIdx.x) >> 5;
    if (warp >= N) return;
    int lane = threadIdx.x & 31;
    int beg = g_off[warp], end = g_off[warp + 1];
    int deg = end - beg;

    float4 sdv = *(const float4*)(g_sd + 4 * warp);
    float e0 = -1e30f, e1 = -1e30f, e2 = -1e30f, e3 = -1e30f;
    int sl = 0;
    if (lane < deg) {
        sl = g_csrc[beg + lane];
        float4 sv = *(const float4*)(g_ss + 4 * sl);
        e0 = lrelu(sv.x + sdv.x); e1 = lrelu(sv.y + sdv.y);
        e2 = lrelu(sv.z + sdv.z); e3 = lrelu(sv.w + sdv.w);
    }
    float m0 = e0, m1 = e1, m2 = e2, m3 = e3;
    for (int i = beg + 32 + lane; i < end; i += 32) {
        int s = g_csrc[i];
        float4 sv = *(const float4*)(g_ss + 4 * s);
        m0 = fmaxf(m0, lrelu(sv.x + sdv.x)); m1 = fmaxf(m1, lrelu(sv.y + sdv.y));
        m2 = fmaxf(m2, lrelu(sv.z + sdv.z)); m3 = fmaxf(m3, lrelu(sv.w + sdv.w));
    }
    #pragma unroll
    for (int o = 16; o > 0; o >>= 1) {
        m0 = fmaxf(m0, __shfl_xor_sync(0xffffffffu, m0, o));
        m1 = fmaxf(m1, __shfl_xor_sync(0xffffffffu, m1, o));
        m2 = fmaxf(m2, __shfl_xor_sync(0xffffffffu, m2, o));
        m3 = fmaxf(m3, __shfl_xor_sync(0xffffffffu, m3, o));
    }

    int hsel = lane >> 3;
    float4 vacc = make_float4(0.f, 0.f, 0.f, 0.f);
    float z0 = 0.f, z1 = 0.f, z2 = 0.f, z3 = 0.f;
    int nf = deg < 32 ? deg : 32;
    for (int i = 0; i < nf; i++) {
        float q0 = __shfl_sync(0xffffffffu, e0, i);
        float q1 = __shfl_sync(0xffffffffu, e1, i);
        float q2 = __shfl_sync(0xffffffffu, e2, i);
        float q3 = __shfl_sync(0xffffffffu, e3, i);
        int s = __shfl_sync(0xffffffffu, sl, i);
        float p0 = __expf(q0 - m0), p1 = __expf(q1 - m1);
        float p2 = __expf(q2 - m2), p3 = __expf(q3 - m3);
        z0 += p0; z1 += p1; z2 += p2; z3 += p3;
        float ph = (hsel == 0) ? p0 : (hsel == 1) ? p1 : (hsel == 2) ? p2 : p3;
        float4 row = *(const float4*)&g_h[(size_t)s * 128 + 4 * lane];
        vacc.x += ph * row.x; vacc.y += ph * row.y;
        vacc.z += ph * row.z; vacc.w += ph * row.w;
    }
    for (int i = beg + 32; i < end; i++) {
        int s = g_csrc[i];
        float4 sv = *(const float4*)(g_ss + 4 * s);
        float p0 = __expf(lrelu(sv.x + sdv.x) - m0), p1 = __expf(lrelu(sv.y + sdv.y) - m1);
        float p2 = __expf(lrelu(sv.z + sdv.z) - m2), p3 = __expf(lrelu(sv.w + sdv.w) - m3);
        z0 += p0; z1 += p1; z2 += p2; z3 += p3;
        float ph = (hsel == 0) ? p0 : (hsel == 1) ? p1 : (hsel == 2) ? p2 : p3;
        float4 row = *(const float4*)&g_h[(size_t)s * 128 + 4 * lane];
        vacc.x += ph * row.x; vacc.y += ph * row.y;
        vacc.z += ph * row.z; vacc.w += ph * row.w;
    }

    float zh = (hsel == 0) ? z0 : (hsel == 1) ? z1 : (hsel == 2) ? z2 : z3;
    float inv = 1.f / (zh + 1e-16f);
    int f = 4 * lane;
    float4 bi = *(const float4*)&bias[f];
    float4 xi = *(const float4*)&xin[(size_t)warp * 128 + f];
    float4 v;
    v.x = vacc.x * inv + bi.x + xi.x;  v.x = v.x > 0.f ? v.x : expm1f(v.x);
    v.y = vacc.y * inv + bi.y + xi.y;  v.y = v.y > 0.f ? v.y : expm1f(v.y);
    v.z = vacc.z * inv + bi.z + xi.z;  v.z = v.z > 0.f ? v.z : expm1f(v.z);
    v.w = vacc.w * inv + bi.w + xi.w;  v.w = v.w > 0.f ? v.w : expm1f(v.w);
    *(float4*)&xout[(size_t)warp * 128 + f] = v;
}

// ---------------- layer-3 small weights: ws[k,h] = sum_f W3[k,h*128+f]*a[h,f]
__global__ void k_wsmall(const float* __restrict__ W3, const float* __restrict__ as3,
                         const float* __restrict__ ad3)
{
    int t = blockIdx.x * blockDim.x + threadIdx.x;
    if (t >= 1024) return;
    int which = t >> 9;
    int idx = t & 511;
    int k = idx >> 2, hh = idx & 3;
    const float* a = which ? ad3 : as3;
    const float* wrow = W3 + (size_t)k * 512 + hh * 128;
    float s = 0.f;
    for (int f = 0; f < 128; f++) s += wrow[f] * a[hh * 128 + f];
    if (which) g_wd[k * 4 + hh] = s; else g_ws[k * 4 + hh] = s;
}

// ---------------- layer-3 scores: s = x2 @ ws / wd ----------------
__global__ void k_scores3(int N)
{
    int warp = (blockIdx.x * blockDim.x + threadIdx.x) >> 5;
    if (warp >= N) return;
    int lane = threadIdx.x & 31;
    const float* xr = g_x2 + (size_t)warp * 128;
    float ps[4] = {0.f, 0.f, 0.f, 0.f}, pd[4] = {0.f, 0.f, 0.f, 0.f};
    #pragma unroll
    for (int kk = 0; kk < 4; kk++) {
        int k = kk * 32 + lane;
        float xv = xr[k];
        #pragma unroll
        for (int hh = 0; hh < 4; hh++) {
            ps[hh] += xv * g_ws[k * 4 + hh];
            pd[hh] += xv * g_wd[k * 4 + hh];
        }
    }
    #pragma unroll
    for (int o = 16; o > 0; o >>= 1)
        #pragma unroll
        for (int hh = 0; hh < 4; hh++) {
            ps[hh] += __shfl_xor_sync(0xffffffffu, ps[hh], o);
            pd[hh] += __shfl_xor_sync(0xffffffffu, pd[hh], o);
        }
    if (lane == 0) {
        #pragma unroll
        for (int hh = 0; hh < 4; hh++) {
            g_ss[warp * 4 + hh] = ps[hh];
            g_sd[warp * 4 + hh] = pd[hh];
        }
    }
}

// ---------------- layer-3 aggregate: agg[n,h*128+k] = sum_e alpha_h x2[src,k]
__global__ void k_agg3(int N)
{
    int warp = (blockIdx.x * blockDim.x + threadIdx.x) >> 5;
    if (warp >= N) return;
    int lane = threadIdx.x & 31;
    int beg = g_off[warp], end = g_off[warp + 1];
    int deg = end - beg;

    float4 sdv = *(const float4*)(g_sd + 4 * warp);
    float e0 = -1e30f, e1 = -1e30f, e2 = -1e30f, e3 = -1e30f;
    int sl = 0;
    if (lane < deg) {
        sl = g_csrc[beg + lane];
        float4 sv = *(const float4*)(g_ss + 4 * sl);
        e0 = lrelu(sv.x + sdv.x); e1 = lrelu(sv.y + sdv.y);
        e2 = lrelu(sv.z + sdv.z); e3 = lrelu(sv.w + sdv.w);
    }
    float m0 = e0, m1 = e1, m2 = e2, m3 = e3;
    for (int i = beg + 32 + lane; i < end; i += 32) {
        int s = g_csrc[i];
        float4 sv = *(const float4*)(g_ss + 4 * s);
        m0 = fmaxf(m0, lrelu(sv.x + sdv.x)); m1 = fmaxf(m1, lrelu(sv.y + sdv.y));
        m2 = fmaxf(m2, lrelu(sv.z + sdv.z)); m3 = fmaxf(m3, lrelu(sv.w + sdv.w));
    }
    #pragma unroll
    for (int o = 16; o > 0; o >>= 1) {
        m0 = fmaxf(m0, __shfl_xor_sync(0xffffffffu, m0, o));
        m1 = fmaxf(m1, __shfl_xor_sync(0xffffffffu, m1, o));
        m2 = fmaxf(m2, __shfl_xor_sync(0xffffffffu, m2, o));
        m3 = fmaxf(m3, __shfl_xor_sync(0xffffffffu, m3, o));
    }

    float4 va0 = make_float4(0,0,0,0), va1 = va0, va2 = va0, va3 = va0;
    float z0 = 0.f, z1 = 0.f, z2 = 0.f, z3 = 0.f;
    int nf = deg < 32 ? deg : 32;
    for (int i = 0; i < nf; i++) {
        float q0 = __shfl_sync(0xffffffffu, e0, i);
        float q1 = __shfl_sync(0xffffffffu, e1, i);
        float q2 = __shfl_sync(0xffffffffu, e2, i);
        float q3 = __shfl_sync(0xffffffffu, e3, i);
        int s = __shfl_sync(0xffffffffu, sl, i);
        float p0 = __expf(q0 - m0), p1 = __expf(q1 - m1);
        float p2 = __expf(q2 - m2), p3 = __expf(q3 - m3);
        z0 += p0; z1 += p1; z2 += p2; z3 += p3;
        float4 row = *(const float4*)&g_x2[(size_t)s * 128 + 4 * lane];
        va0.x += p0*row.x; va0.y += p0*row.y; va0.z += p0*row.z; va0.w += p0*row.w;
        va1.x += p1*row.x; va1.y += p1*row.y; va1.z += p1*row.z; va1.w += p1*row.w;
        va2.x += p2*row.x; va2.y += p2*row.y; va2.z += p2*row.z; va2.w += p2*row.w;
        va3.x += p3*row.x; va3.y += p3*row.y; va3.z += p3*row.z; va3.w += p3*row.w;
    }
    for (int i = beg + 32; i < end; i++) {
        int s = g_csrc[i];
        float4 sv = *(const float4*)(g_ss + 4 * s);
        float p0 = __expf(lrelu(sv.x + sdv.x) - m0), p1 = __expf(lrelu(sv.y + sdv.y) - m1);
        float p2 = __expf(lrelu(sv.z + sdv.z) - m2), p3 = __expf(lrelu(sv.w + sdv.w) - m3);
        z0 += p0; z1 += p1; z2 += p2; z3 += p3;
        float4 row = *(const float4*)&g_x2[(size_t)s * 128 + 4 * lane];
        va0.x += p0*row.x; va0.y += p0*row.y; va0.z += p0*row.z; va0.w += p0*row.w;
        va1.x += p1*row.x; va1.y += p1*row.y; va1.z += p1*row.z; va1.w += p1*row.w;
        va2.x += p2*row.x; va2.y += p2*row.y; va2.z += p2*row.z; va2.w += p2*row.w;
        va3.x += p3*row.x; va3.y += p3*row.y; va3.z += p3*row.z; va3.w += p3*row.w;
    }

    float i0 = 1.f/(z0+1e-16f), i1 = 1.f/(z1+1e-16f), i2 = 1.f/(z2+1e-16f), i3 = 1.f/(z3+1e-16f);
    size_t base = (size_t)warp * 512 + 4 * lane;
    *(float4*)&g_agg[base]       = make_float4(va0.x*i0, va0.y*i0, va0.z*i0, va0.w*i0);
    *(float4*)&g_agg[base + 128] = make_float4(va1.x*i1, va1.y*i1, va1.z*i1, va1.w*i1);
    *(float4*)&g_agg[base + 256] = make_float4(va2.x*i2, va2.y*i2, va2.z*i2, va2.w*i2);
    *(float4*)&g_agg[base + 384] = make_float4(va3.x*i3, va3.y*i3, va3.z*i3, va3.w*i3);
}

// ---------------- host entry ----------------
extern "C" void kernel_launch(void* const* d_in, const int* in_sizes, int n_in,
                              void* d_out, int out_size)
{
    const float* x   = (const float*)d_in[0];
    const void*  ei  = d_in[1];
    const float* W1  = (const float*)d_in[2];
    const float* as1 = (const float*)d_in[3];
    const float* ad1 = (const float*)d_in[4];
    const float* b1  = (const float*)d_in[5];
    const float* W2  = (const float*)d_in[6];
    const float* as2 = (const float*)d_in[7];
    const float* ad2 = (const float*)d_in[8];
    const float* b2  = (const float*)d_in[9];
    const float* W3  = (const float*)d_in[10];
    const float* as3 = (const float*)d_in[11];
    const float* ad3 = (const float*)d_in[12];
    const float* b3  = (const float*)d_in[13];

    int N = in_sizes[0] / 128;
    int E = in_sizes[1] / 2;

    int nb = (N + 1023) / 1024;
    int nsamp = (2 * E < 8192) ? 2 * E : 8192;

    // edge dtype detect + CSR build
    k_detect<<<1, 512>>>((const int*)ei, nsamp);
    k_init_cnt<<<nb, 1024>>>(N);
    k_hist<<<(E + 255) / 256, 256>>>(ei, E, N);
    k_scan1<<<nb, 1024>>>(N);
    k_scan2<<<1, 1024>>>(nb);
    k_scan3<<<nb, 1024>>>(N);
    k_scatter<<<(E + N + 255) / 256, 256>>>(ei, E, N);

    int gemmBlocks = (N + 127) / 128;
    int aggBlocks  = (N + 7) / 8;   // 8 warps (nodes) per 256-thread block

    // layer 1 (bf16x2 3-term + fused scores)
    k_gemm12<0><<<gemmBlocks, 256>>>(x, W1, as1, ad1, N);
    k_agg<1><<<aggBlocks, 256>>>(x, b1, N);

    // layer 2
    k_gemm12<1><<<gemmBlocks, 256>>>(nullptr, W2, as2, ad2, N);
    k_agg<2><<<aggBlocks, 256>>>(nullptr, b2, N);

    // layer 3 (never materializes h3 = [N,4,128])
    k_wsmall<<<4, 256>>>(W3, as3, ad3);
    k_scores3<<<aggBlocks, 256>>>(N);
    k_agg3<<<aggBlocks, 256>>>(N);
    k_gemm3<<<gemmBlocks, 256>>>(W3, (float*)d_out, b3, N);
}